// round 15
// baseline (speedup 1.0000x reference)
#include <cuda_runtime.h>
#include <cuda_bf16.h>
#include <cuda_fp16.h>
#include <math.h>
#include <stdint.h>

// Problem constants
#define BB 512
#define KK 256
#define NN 512
#define CC 6
#define J4 (KK/4)       // 64 super-groups of 4 k's
#define TPB 128         // threads per block; each thread owns 4 tracks

#define LOG2E_F 1.4426950408889634f
#define LN2_F   0.6931471805599453f
#define LOG2PI_LOG2E_F 2.6514961294723187f  // log2(2*pi)
#define RQ2_F 0.72134752044448170f          // 0.5 * log2(e)

// ---------------- scratch (static device globals; no allocation) -------------
__device__ double4 g_part[BB];           // {spatial, efs, cnt, lam} per batch
__device__ unsigned int g_done = 0;

// ---------------- fast math helpers ------------------------------------------
__device__ __forceinline__ float ex2f(float x) {
    float y; asm("ex2.approx.ftz.f32 %0, %1;" : "=f"(y) : "f"(x)); return y;
}
__device__ __forceinline__ float lg2f(float x) {
    float y; asm("lg2.approx.ftz.f32 %0, %1;" : "=f"(y) : "f"(x)); return y;
}
// dual-half exp2: one MUFU op computes 2^x for both halves
__device__ __forceinline__ __half2 h2ex2(__half2 x) {
    uint32_t xi = *reinterpret_cast<uint32_t*>(&x), yi;
    asm("ex2.approx.f16x2 %0, %1;" : "=r"(yi) : "r"(xi));
    return *reinterpret_cast<__half2*>(&yi);
}
__device__ __forceinline__ __half2 u2h2(uint32_t u) {
    return *reinterpret_cast<__half2*>(&u);
}
__device__ __forceinline__ double warpRedD(double v) {
    #pragma unroll
    for (int o = 16; o; o >>= 1) v += __shfl_down_sync(0xffffffffu, v, o);
    return v;
}

// ---------------- templated hot loop: M tracks x 4 k's per iteration ----------
template <int M>
__device__ __forceinline__ void kloop(
    const float4* __restrict__ scA,     // {c0,c1,c2,c3} per k
    const float4* __restrict__ scC,     // {c4,c5} x2 per float4, 2 per j2
    const uint2* const* cep,            // per-track ce base (sce4 + g)
    const float* x0, const float* x1,
    float* s, float* t)
{
    const __half2 hz = __floats2half2_rn(0.f, 0.f);
    for (int J = 0; J < J4; J += 8) {
        __half2 sh[M], th[M];
        #pragma unroll
        for (int m = 0; m < M; m++) { sh[m] = hz; th[m] = hz; }
        #pragma unroll 2
        for (int j2 = J; j2 < J + 8; j2++) {
            const float4 a0 = scA[4 * j2 + 0];
            const float4 a1 = scA[4 * j2 + 1];
            const float4 a2 = scA[4 * j2 + 2];
            const float4 a3 = scA[4 * j2 + 3];
            const float4 cA = scC[2 * j2 + 0];   // {c4_0,c5_0,c4_1,c5_1}
            const float4 cB = scC[2 * j2 + 1];   // {c4_2,c5_2,c4_3,c5_3}
            #pragma unroll
            for (int m = 0; m < M; m++) {
                const uint2 ceu = cep[m][j2 * CC];   // half4: ce for 4 k's
                const float xm = x0[m], ym = x1[m];

                // Horner: q = c0 + (c1 + c3*x)*x + (c2 + c5*x + c4*y)*y
                float u1 = fmaf(a0.w, xm, a0.y);
                float u2 = fmaf(cA.y, xm, a0.z);
                u2 = fmaf(cA.x, ym, u2);
                float q0 = fmaf(u1, xm, a0.x);
                q0 = fmaf(u2, ym, q0);

                float v1 = fmaf(a1.w, xm, a1.y);
                float v2 = fmaf(cA.w, xm, a1.z);
                v2 = fmaf(cA.z, ym, v2);
                float q1 = fmaf(v1, xm, a1.x);
                q1 = fmaf(v2, ym, q1);

                float w1 = fmaf(a2.w, xm, a2.y);
                float w2 = fmaf(cB.y, xm, a2.z);
                w2 = fmaf(cB.x, ym, w2);
                float q2 = fmaf(w1, xm, a2.x);
                q2 = fmaf(w2, ym, q2);

                float z1 = fmaf(a3.w, xm, a3.y);
                float z2 = fmaf(cB.w, xm, a3.z);
                z2 = fmaf(cB.z, ym, z2);
                float q3 = fmaf(z1, xm, a3.x);
                q3 = fmaf(z2, ym, q3);

                __half2 p01 = h2ex2(__floats2half2_rn(q0, q1));
                __half2 p23 = h2ex2(__floats2half2_rn(q2, q3));

                sh[m] = __hadd2(sh[m], p01);
                sh[m] = __hadd2(sh[m], p23);
                th[m] = __hfma2(p01, u2h2(ceu.x), th[m]);
                th[m] = __hfma2(p23, u2h2(ceu.y), th[m]);
            }
        }
        #pragma unroll
        for (int m = 0; m < M; m++) {
            float2 f;
            f = __half22float2(sh[m]); s[m] += f.x + f.y;
            f = __half22float2(th[m]); t[m] += f.x + f.y;
        }
    }
}

// ---------------- main kernel (fully fused, 1 block per batch) ----------------
__global__ __launch_bounds__(TPB) void main_kernel(
    const float* __restrict__ pi,
    const float* __restrict__ mu,
    const float* __restrict__ L,
    const float* __restrict__ ef_logits,
    const float* __restrict__ tracks,
    const uint32_t* __restrict__ mask,
    float* __restrict__ out)
{
    const int b   = blockIdx.x;
    const int tid = threadIdx.x;

    __shared__ float4 scA[KK];           // {c0,c1,c2,c3} per k          4 KB
    __shared__ float4 scC[2 * J4];       // {c4,c5} pairs per 4-k group  2 KB
    __shared__ uint2  sce4[J4 * CC];     // half4 ce per (j2, g)         3 KB
    __shared__ double red[4 * 4];
    __shared__ bool   isLast;

    // Lambda contribution (each thread covers 2 k's)
    double lam = (double)pi[(size_t)b * KK + tid] + (double)pi[(size_t)b * KK + tid + TPB];

    // prefix-mask property: first track inactive => whole batch empty
    const bool blockActive = (mask[(size_t)b * NN] != 0u);

    double spatial = 0.0, efs = 0.0, cnt = 0.0;

    if (blockActive) {
        // ---- staging (float): thread tid builds coefficients for k=tid, tid+128 ----
        #pragma unroll
        for (int kk = 0; kk < 2; kk++) {
            const int k = tid + kk * TPB;
            const int i = b * KK + k;
            float pv = pi[i];
            float a  = L[i * 4 + 0];
            float bb = L[i * 4 + 2];
            float c  = L[i * 4 + 3];
            float m0 = mu[i * 2 + 0];
            float m1 = mu[i * 2 + 1];

            float base2 = lg2f(pv) - LOG2PI_LOG2E_F - lg2f(a * c);  // < 0

            float A2  = RQ2_F / (a * a);
            float Cr2 = RQ2_F / (c * c);
            float BA  = bb / a;
            float P = fmaf(Cr2 * BA, BA, A2);
            float Q = Cr2;
            float R = -2.0f * Cr2 * BA;

            float4 v4;
            v4.x = base2 - P * m0 * m0 - Q * m1 * m1 - R * m0 * m1;
            v4.y = fmaf(2.0f * P, m0, R * m1);
            v4.z = fmaf(2.0f * Q, m1, R * m0);
            v4.w = -P;
            scA[k] = v4;

            const int j2 = k >> 2, slot = k & 3;
            float* fC = (float*)scC;
            fC[j2 * 8 + slot * 2 + 0] = -Q;
            fC[j2 * 8 + slot * 2 + 1] = -R;

            // CE table: lse(ef_logits) - ef_logits[c], half4 per (j2,g) layout
            float e[CC];
            float mx = -INFINITY;
            #pragma unroll
            for (int c2 = 0; c2 < CC; c2++) {
                e[c2] = ef_logits[(size_t)i * CC + c2];
                mx = fmaxf(mx, e[c2]);
            }
            float ssum = 0.f;
            #pragma unroll
            for (int c2 = 0; c2 < CC; c2++) ssum += ex2f((e[c2] - mx) * LOG2E_F);
            float lse = mx + lg2f(ssum) * LN2_F;
            __half* hce = reinterpret_cast<__half*>(sce4);
            #pragma unroll
            for (int c2 = 0; c2 < CC; c2++)
                hce[(j2 * CC + c2) * 4 + slot] = __float2half_rn(lse - e[c2]);
        }
        __syncthreads();

        // ---- per-track pass: thread owns tracks tid + 128*m, m=0..3 ----
        bool act[4];
        float x0[4], x1[4];
        const uint2* cep[4];
        float s[4], t[4];
        int G = 0;  // active track-groups for this warp (prefix => contiguous)
        #pragma unroll
        for (int m = 0; m < 4; m++) {
            const int n = tid + m * TPB;
            act[m] = (mask[(size_t)b * NN + n] != 0u);
            if (__ballot_sync(0xffffffffu, act[m]) != 0u) G = m + 1;
            x0[m] = 0.f; x1[m] = 0.f;
            cep[m] = sce4;
            s[m] = 0.f; t[m] = 0.f;
        }
        #pragma unroll
        for (int m = 0; m < 4; m++) {
            if (m < G) {
                const float* tr = tracks + ((size_t)b * NN + tid + m * TPB) * 6;
                x0[m] = tr[0];
                x1[m] = tr[1];
                cep[m] = sce4 + (int)tr[5];
            }
        }

        switch (G) {
            case 4: kloop<4>(scA, scC, cep, x0, x1, s, t); break;
            case 3: kloop<3>(scA, scC, cep, x0, x1, s, t); break;
            case 2: kloop<2>(scA, scC, cep, x0, x1, s, t); break;
            case 1: kloop<1>(scA, scC, cep, x0, x1, s, t); break;
            default: break;
        }

        #pragma unroll
        for (int m = 0; m < 4; m++) {
            if (act[m]) {
                spatial -= (double)(lg2f(s[m]) * LN2_F);
                efs     += (double)(t[m] / s[m]);
                cnt     += 1.0;
            }
        }
    }

    // ---- block reduce 4 doubles (uniform control, 4 warps) ----
    spatial = warpRedD(spatial);
    efs     = warpRedD(efs);
    cnt     = warpRedD(cnt);
    lam     = warpRedD(lam);
    const int wid = tid >> 5, lid = tid & 31;
    if (lid == 0) {
        red[wid]      = spatial;
        red[4 + wid]  = efs;
        red[8 + wid]  = cnt;
        red[12 + wid] = lam;
    }
    __syncthreads();
    if (tid == 0) {
        double s0 = 0, s1 = 0, s2 = 0, s3 = 0;
        #pragma unroll
        for (int w = 0; w < 4; w++) {
            s0 += red[w]; s1 += red[4 + w]; s2 += red[8 + w]; s3 += red[12 + w];
        }
        g_part[b] = make_double4(s0, s1, s2, s3);
    }

    // ---- last-block-done finalize (deterministic fixed-order sum) ----
    __threadfence();
    if (tid == 0) {
        unsigned int v = atomicAdd(&g_done, 1u);
        isLast = (v == (unsigned)BB - 1u);
    }
    __syncthreads();
    if (isLast) {
        double lamSum = 0, cntSum = 0, l1Sum = 0, spSum = 0, efSum = 0;
        for (int b2 = tid; b2 < BB; b2 += TPB) {
            double4 e0 = g_part[b2];
            lamSum += e0.w;
            cntSum += e0.z;
            l1Sum  += fabs(e0.w - e0.z) * sqrt(e0.z + 1.0);
            spSum  += e0.x;
            efSum  += e0.y;
        }
        lamSum = warpRedD(lamSum);
        cntSum = warpRedD(cntSum);
        l1Sum  = warpRedD(l1Sum);
        spSum  = warpRedD(spSum);
        efSum  = warpRedD(efSum);
        __syncthreads();
        __shared__ double red5[4 * 5];
        if (lid == 0) {
            red5[wid]      = lamSum;
            red5[4 + wid]  = cntSum;
            red5[8 + wid]  = l1Sum;
            red5[12 + wid] = spSum;
            red5[16 + wid] = efSum;
        }
        __syncthreads();
        if (tid == 0) {
            double a0 = 0, a1 = 0, a2 = 0, a3 = 0, a4 = 0;
            #pragma unroll
            for (int w = 0; w < 4; w++) {
                a0 += red5[w]; a1 += red5[4 + w]; a2 += red5[8 + w];
                a3 += red5[12 + w]; a4 += red5[16 + w];
            }
            double count_loss = a0 / (double)BB;
            double n_total    = a1 > 1.0 ? a1 : 1.0;
            double count_l1   = a2 / (double)BB;
            double spatialL   = a3 / n_total;
            double efL        = a4 / n_total;
            double total = count_loss + spatialL + efL + count_l1;
            out[0] = (float)total;
            out[1] = (float)spatialL;
            out[2] = (float)count_loss;
            out[3] = (float)count_l1;
            out[4] = (float)efL;
            g_done = 0;  // reset for next graph replay
        }
    }
}

// ---------------- launch -------------------------------------------------------
extern "C" void kernel_launch(void* const* d_in, const int* in_sizes, int n_in,
                              void* d_out, int out_size) {
    const float* pi        = (const float*)d_in[0];
    const float* mu        = (const float*)d_in[1];
    const float* L         = (const float*)d_in[2];
    const float* ef_logits = (const float*)d_in[3];
    const float* tracks    = (const float*)d_in[4];
    const uint32_t* mask   = (const uint32_t*)d_in[5];

    main_kernel<<<BB, TPB>>>(pi, mu, L, ef_logits, tracks, mask, (float*)d_out);
}